// round 15
// baseline (speedup 1.0000x reference)
#include <cuda_runtime.h>
#include <cuda_bf16.h>
#include <cuda_fp16.h>
#include <cstdint>
#include <cstddef>

// Problem constants
#define S_TOK 8192
#define M_DIM 512
#define H_DIM 1024
#define N_EXP 8
#define CAP   1024

// ---------------- portable PTX helpers (sm_103 baseline) ------------------------
__device__ __forceinline__ uint32_t smem_to_u32(const void* p) {
    uint32_t a;
    asm("{ .reg .u64 t; cvta.to.shared.u64 t, %1; cvt.u32.u64 %0, t; }" : "=r"(a) : "l"(p));
    return a;
}
#define CP_ASYNC16(dst, src) \
    asm volatile("cp.async.cg.shared.global [%0], [%1], 16;" :: "r"(dst), "l"(src))
#define CP_COMMIT() asm volatile("cp.async.commit_group;" ::: "memory")
#define CP_WAIT1()  asm volatile("cp.async.wait_group 1;" ::: "memory")
#define CP_WAIT0()  asm volatile("cp.async.wait_group 0;" ::: "memory")
#define LDSM_X4(r, addr) \
    asm volatile("ldmatrix.sync.aligned.m8n8.x4.shared.b16 {%0,%1,%2,%3}, [%4];" \
        : "=r"((r)[0]), "=r"((r)[1]), "=r"((r)[2]), "=r"((r)[3]) : "r"(addr))
#define MMA_F16(c, a, b0, b1) \
    asm volatile("mma.sync.aligned.m16n8k16.row.col.f32.f16.f16.f32 " \
        "{%0,%1,%2,%3}, {%4,%5,%6,%7}, {%8,%9}, {%0,%1,%2,%3};" \
        : "+f"((c)[0]), "+f"((c)[1]), "+f"((c)[2]), "+f"((c)[3]) \
        : "r"((a)[0]), "r"((a)[1]), "r"((a)[2]), "r"((a)[3]), "r"(b0), "r"(b1))

// ---------------- device scratch ------------------------------------------------
__device__ __half g_a[(size_t)N_EXP * CAP * M_DIM];            // gathered tokens fp16
__device__ __half g_h[(size_t)N_EXP * CAP * H_DIM];            // hidden fp16
__device__ __half g_w1t[(size_t)N_EXP * H_DIM * M_DIM];        // w1^T fp16 [E,H,M]
__device__ __half g_w2t[(size_t)N_EXP * M_DIM * H_DIM];        // w2^T fp16 [E,M,H]
__device__ float g_gates[(size_t)S_TOK * N_EXP];
__device__ float g_gate[S_TOK];
__device__ int   g_expert[S_TOK];
__device__ int   g_loc[S_TOK];
__device__ int   g_slot[N_EXP * CAP];
__device__ int   g_cnt1[N_EXP * (CAP / 128)];   // GEMM1 row-block completion (target 8)
__device__ int   g_w2done;                      // w2 transpose blocks done (target 4096)

// ---------------- 1) fused prep: gate + w1 transpose ----------------------------
__global__ void prep_kernel(const float* __restrict__ feats, const float* __restrict__ wg,
                            const float* __restrict__ w1) {
    __shared__ float sh[N_EXP * M_DIM];   // 16KB
    int bid = blockIdx.x;
    int tid = threadIdx.x;

    if (bid < S_TOK / 8) {
        // ---- gate role ----
        for (int i = tid; i < N_EXP * M_DIM; i += 256) {
            int m = i & (M_DIM - 1);
            int e = i >> 9;
            sh[e * M_DIM + m] = wg[m * N_EXP + e];
        }
        __syncthreads();
        int warp = tid >> 5, lane = tid & 31;
        int s = bid * 8 + warp;
        const float* frow = feats + (size_t)s * M_DIM;
        float x[16];
#pragma unroll
        for (int j = 0; j < 16; j++) x[j] = frow[lane + 32 * j];
        float logit[N_EXP];
#pragma unroll
        for (int e = 0; e < N_EXP; e++) {
            const float* w = sh + e * M_DIM;
            float acc = 0.f;
#pragma unroll
            for (int j = 0; j < 16; j++) acc += x[j] * w[lane + 32 * j];
#pragma unroll
            for (int off = 16; off > 0; off >>= 1)
                acc += __shfl_down_sync(0xffffffffu, acc, off);
            logit[e] = acc;
        }
        if (lane == 0) {
            float mx = logit[0]; int am = 0;
#pragma unroll
            for (int e = 1; e < N_EXP; e++)
                if (logit[e] > mx) { mx = logit[e]; am = e; }
            float ex[N_EXP]; float se = 0.f;
#pragma unroll
            for (int e = 0; e < N_EXP; e++) { ex[e] = expf(logit[e] - mx); se += ex[e]; }
            float inv = 1.f / se;
#pragma unroll
            for (int e = 0; e < N_EXP; e++) g_gates[(size_t)s * N_EXP + e] = ex[e] * inv;
            g_expert[s] = am;
            g_gate[s]   = ex[am] * inv;
        }
        return;
    }

    // ---- w1 transpose role: [E,M,H] -> [E,H,M] ---------------------------------
    int tb = bid - S_TOK / 8;
    const int R = M_DIM, C = H_DIM;
    int cx = tb & 31, cy = (tb >> 5) & 15, e = tb >> 9;
    int r0 = cy * 32, c0 = cx * 32;
    float (*t)[33] = (float(*)[33])sh;
    int tx = tid & 31, ty = tid >> 5;        // 32 x 8
    const float* ine = w1 + (size_t)e * R * C;
#pragma unroll
    for (int i = 0; i < 4; i++)
        t[ty + i * 8][tx] = ine[(size_t)(r0 + ty + i * 8) * C + c0 + tx];
    __syncthreads();
    __half* oe = g_w1t + (size_t)e * R * C;
#pragma unroll
    for (int it = 0; it < 2; it++) {
        int idx = it * 256 + tid;
        int ci  = idx >> 4;
        int rp  = (idx & 15) * 2;
        __half2 v = __floats2half2_rn(t[rp][ci], t[rp + 1][ci]);
        *(__half2*)(oe + (size_t)(c0 + ci) * R + r0 + rp) = v;
    }
}

// ---------------- 2) parallel capacity scan + fused l_aux + counter reset -------
__global__ void scan_kernel(float* __restrict__ laux_out, int write_laux) {
    __shared__ int sexp[S_TOK];          // 32KB
    __shared__ int cnt[32][N_EXP];
    __shared__ int off[32][N_EXP];
    __shared__ int tot[N_EXP];
    __shared__ float red[1024];
    int tid = threadIdx.x;
    int warp = tid >> 5, lane = tid & 31;
    unsigned ltmask = (lane == 0) ? 0u : (0xffffffffu >> (32 - lane));

    // reset dependency counters for this invocation (graph-replay safe)
    if (tid < N_EXP * (CAP / 128)) g_cnt1[tid] = 0;
    if (tid == 64) g_w2done = 0;

    for (int i = tid; i < S_TOK; i += 1024) sexp[i] = g_expert[i];
    for (int i = tid; i < N_EXP * CAP; i += 1024) g_slot[i] = -1;
    __syncthreads();

    // Phase 1: counts
    {
        int run[N_EXP];
#pragma unroll
        for (int e = 0; e < N_EXP; e++) run[e] = 0;
#pragma unroll
        for (int it = 0; it < 8; it++) {
            int s = warp * 256 + it * 32 + lane;
            int e = sexp[s];
#pragma unroll
            for (int eq = 0; eq < N_EXP; eq++) {
                unsigned bal = __ballot_sync(0xffffffffu, e == eq);
                run[eq] += __popc(bal);
            }
        }
        if (lane < N_EXP) cnt[warp][lane] = run[lane];
    }
    __syncthreads();

    // Phase 2: exclusive prefix + totals
    if (tid < 256) {
        int w = tid >> 3, e = tid & 7;
        int acc = 0;
        for (int wp = 0; wp < w; wp++) acc += cnt[wp][e];
        off[w][e] = acc;
        if (w == 31) tot[e] = acc + cnt[31][e];
    }
    __syncthreads();

    // Phase 3: assignment
    {
        int run[N_EXP];
#pragma unroll
        for (int e = 0; e < N_EXP; e++) run[e] = off[warp][e];
#pragma unroll
        for (int it = 0; it < 8; it++) {
            int s = warp * 256 + it * 32 + lane;
            int e = sexp[s];
            int myrank = 0;
            unsigned bals[N_EXP];
#pragma unroll
            for (int eq = 0; eq < N_EXP; eq++) {
                bals[eq] = __ballot_sync(0xffffffffu, e == eq);
                if (e == eq) myrank = __popc(bals[eq] & ltmask);
            }
            int loc = run[e] + myrank;
            g_loc[s] = loc;
            if (loc < CAP) g_slot[e * CAP + loc] = s;
#pragma unroll
            for (int eq = 0; eq < N_EXP; eq++) run[eq] += __popc(bals[eq]);
        }
    }

    // Fused l_aux
    if (!write_laux) return;
    float w[N_EXP];
#pragma unroll
    for (int e = 0; e < N_EXP; e++) w[e] = (float)min(tot[e], CAP);
    float acc = 0.f;
    for (int s = tid; s < S_TOK; s += 1024) {
        const float4* gp = (const float4*)(g_gates + (size_t)s * N_EXP);
        float4 a = gp[0], b = gp[1];
        acc += a.x * w[0] + a.y * w[1] + a.z * w[2] + a.w * w[3]
             + b.x * w[4] + b.y * w[5] + b.z * w[6] + b.w * w[7];
    }
    red[tid] = acc;
    __syncthreads();
    for (int st = 512; st > 0; st >>= 1) {
        if (tid < st) red[tid] += red[tid + st];
        __syncthreads();
    }
    if (tid == 0)
        *laux_out = red[0] * (float)N_EXP / ((float)S_TOK * (float)S_TOK);
}

// ---------------- 3) fused gather + zero-dropped --------------------------------
__global__ void gather_zero_kernel(const float* __restrict__ feats, float* __restrict__ out) {
    int bid = blockIdx.x;
    int tid = threadIdx.x;   // 128
    if (bid < N_EXP * CAP) {
        int token = g_slot[bid];
        float4 v = make_float4(0.f, 0.f, 0.f, 0.f);
        if (token >= 0) v = ((const float4*)(feats + (size_t)token * M_DIM))[tid];
        __half2 h01 = __floats2half2_rn(v.x, v.y);
        __half2 h23 = __floats2half2_rn(v.z, v.w);
        uint2 hv;
        hv.x = *reinterpret_cast<uint32_t*>(&h01);
        hv.y = *reinterpret_cast<uint32_t*>(&h23);
        ((uint2*)(g_a + (size_t)bid * M_DIM))[tid] = hv;
    } else {
        int s = (bid - N_EXP * CAP) * 4 + (tid >> 5);
        if (g_loc[s] < CAP) return;
        int lane = tid & 31;
        float4* row = (float4*)(out + (size_t)s * M_DIM);
#pragma unroll
        for (int i = 0; i < 4; i++)
            row[lane + 32 * i] = make_float4(0.f, 0.f, 0.f, 0.f);
    }
}

// ---------------- GEMM tile body (shared by both GEMMs) -------------------------
template <int KTOT, bool IS_G1>
__device__ __forceinline__ void gemm_tile_body(
    int tileid, char* smem,
    const __half* __restrict__ a_in, const __half* __restrict__ b_in,
    const float* __restrict__ bias, float* __restrict__ out) {
    constexpr int NTOT = IS_G1 ? H_DIM : M_DIM;
    constexpr int BK = 64;
    constexpr int NC = KTOT / BK;
    constexpr int STG = 32768;
    const uint32_t sbu = smem_to_u32(smem);
    const int t = threadIdx.x;
    const int lane = t & 31, wid = t >> 5;
    const int wm = wid >> 1, wn = wid & 1;
    const int nt = tileid % (NTOT / 128);
    const int mt = (tileid / (NTOT / 128)) % (CAP / 128);
    const int e  = tileid / ((NTOT / 128) * (CAP / 128));

    const __half* srcs[2] = {
        a_in + ((size_t)e * CAP  + mt * 128) * KTOT,
        b_in + ((size_t)e * NTOT + nt * 128) * KTOT};

    auto load_stage = [&](int c, int stg) {
        int k0 = c * BK;
        uint32_t sb = sbu + stg * STG;
#pragma unroll
        for (int i = 0; i < 16; i++) {
            int idx  = i * 128 + t;
            int tile = idx >> 10;
            int rem  = idx & 1023;
            int row  = rem >> 3;
            int seg  = rem & 7;
            const __half* src = srcs[tile] + (size_t)row * KTOT + k0 + seg * 8;
            uint32_t dst = sb + tile * 16384 + row * 128 + (((seg ^ (row & 7))) << 4);
            CP_ASYNC16(dst, src);
        }
        CP_COMMIT();
    };

    float acc[4][8][4];
#pragma unroll
    for (int i = 0; i < 4; i++)
#pragma unroll
        for (int j = 0; j < 8; j++)
#pragma unroll
            for (int k = 0; k < 4; k++) acc[i][j][k] = 0.f;

    load_stage(0, 0);
    load_stage(1, 1);

    const int a_m = wm * 64 + (lane & 15);
    const int b_n = wn * 64 + ((lane >> 3) & 1) * 8 + (lane & 7);
    const int k8l = lane >> 4;

    for (int c = 0; c < NC; c++) {
        if (c >= NC - 1) { CP_WAIT0(); } else { CP_WAIT1(); }
        __syncthreads();
        if (c + 2 < NC) load_stage(c + 2, (c + 2) % 3);

        uint32_t sb = sbu + (c % 3) * STG;
#pragma unroll
        for (int ks = 0; ks < 4; ks++) {
            int seg = ks * 2 + k8l;
            uint32_t A[4][4], B[4][4];
#pragma unroll
            for (int mf = 0; mf < 4; mf++) {
                int m = a_m + mf * 16;
                LDSM_X4(A[mf], sb + m * 128 + ((seg ^ (m & 7)) << 4));
            }
#pragma unroll
            for (int p = 0; p < 4; p++) {
                int n = b_n + p * 16;
                LDSM_X4(B[p], sb + 16384 + n * 128 + ((seg ^ (n & 7)) << 4));
            }
#pragma unroll
            for (int mf = 0; mf < 4; mf++) {
#pragma unroll
                for (int p = 0; p < 4; p++) {
                    MMA_F16(acc[mf][2 * p + 0], A[mf], B[p][0], B[p][2]);
                    MMA_F16(acc[mf][2 * p + 1], A[mf], B[p][1], B[p][3]);
                }
            }
        }
    }

    const int g = lane >> 2, q = lane & 3;
    if (IS_G1) {
#pragma unroll
        for (int mf = 0; mf < 4; mf++) {
#pragma unroll
            for (int h = 0; h < 2; h++) {
                int slotrow = mt * 128 + wm * 64 + mf * 16 + g + h * 8;
                size_t rowbase = ((size_t)e * CAP + slotrow) * H_DIM;
#pragma unroll
                for (int nf = 0; nf < 8; nf++) {
                    int col = nt * 128 + wn * 64 + nf * 8 + q * 2;
                    float v0 = fmaxf(acc[mf][nf][2 * h + 0] + __ldg(&bias[e * NTOT + col]),     0.f);
                    float v1 = fmaxf(acc[mf][nf][2 * h + 1] + __ldg(&bias[e * NTOT + col + 1]), 0.f);
                    __half2 hh = __floats2half2_rn(v0, v1);
                    *reinterpret_cast<uint32_t*>(&g_h[rowbase + col]) =
                        *reinterpret_cast<uint32_t*>(&hh);
                }
            }
        }
    } else {
#pragma unroll
        for (int mf = 0; mf < 4; mf++) {
#pragma unroll
            for (int h = 0; h < 2; h++) {
                int slotrow = mt * 128 + wm * 64 + mf * 16 + g + h * 8;
                int token = g_slot[e * CAP + slotrow];
                if (token < 0) continue;
                float gt = g_gate[token];
                float* orow = out + (size_t)token * M_DIM;
#pragma unroll
                for (int nf = 0; nf < 8; nf++) {
                    int col = nt * 128 + wn * 64 + nf * 8 + q * 2;
                    float2 v;
                    v.x = (acc[mf][nf][2 * h + 0] + __ldg(&bias[e * NTOT + col]))     * gt;
                    v.y = (acc[mf][nf][2 * h + 1] + __ldg(&bias[e * NTOT + col + 1])) * gt;
                    *(float2*)(orow + col) = v;
                }
            }
        }
    }
}

// ---------------- 4) fused FFN: GEMM1 -> w2 transpose -> GEMM2 (one grid) -------
// bids [0,512): GEMM1 tiles (signal g_cnt1[row] after fenced epilogue)
// bids [512,4608): w2 transpose blocks (signal g_w2done)
// bids [4608,4864): GEMM2 tiles (volatile-spin until row's GEMM1 tiles + all
// transposes complete). Producers occupy lower bids -> dispatched first; resident
// producers never wait -> no cyclic dependency.
#define G1_TILES 512
#define W2_BLKS  4096
#define G2_TILES 256

__global__ void __launch_bounds__(128, 2)
moe_ffn_fused(const __half* __restrict__ a_in, const __half* __restrict__ w1t,
              const float* __restrict__ b1, const __half* __restrict__ h_in,
              const __half* __restrict__ w2t, const float* __restrict__ b2,
              const float* __restrict__ w2src, float* __restrict__ out) {
    extern __shared__ __align__(1024) char smem[];
    const int bid = blockIdx.x;
    const int t = threadIdx.x;

    if (bid < G1_TILES) {
        gemm_tile_body<M_DIM, true>(bid, smem, a_in, w1t, b1, nullptr);
        __syncthreads();
        __threadfence();
        if (t == 0) atomicAdd(&g_cnt1[bid >> 3], 1);    // 8 nt tiles per row block
        return;
    }

    if (bid < G1_TILES + W2_BLKS) {
        // ---- w2 transpose: [E,H,M] -> [E,M,H], 32x32 tiles ---------------------
        int tb = bid - G1_TILES;
        const int R = H_DIM, C = M_DIM;
        int cx = tb & 15, cy = (tb >> 4) & 31, e = tb >> 9;
        int r0 = cy * 32, c0 = cx * 32;
        float (*tt)[33] = (float(*)[33])smem;
        int tx = t & 31, ty = t >> 5;        // 32 x 4
        const float* ine = w2src + (size_t)e * R * C;
#pragma unroll
        for (int i = 0; i < 8; i++)
            tt[ty + i * 4][tx] = ine[(size_t)(r0 + ty + i * 4) * C + c0 + tx];
        __syncthreads();
        __half* oe = g_w2t + (size_t)e * R * C;
#pragma unroll
        for (int it = 0; it < 4; it++) {
            int idx = it * 128 + t;
            int ci  = idx >> 4;
            int rp  = (idx & 15) * 2;
            __half2 v = __floats2half2_rn(tt[rp][ci], tt[rp + 1][ci]);
            *(__half2*)(oe + (size_t)(c0 + ci) * R + r0 + rp) = v;
        }
        __syncthreads();
        __threadfence();
        if (t == 0) atomicAdd(&g_w2done, 1);
        return;
    }

    // ---- GEMM2 tile: wait for dependencies, then compute -----------------------
    int tileid = bid - G1_TILES - W2_BLKS;
    int row = tileid >> 2;                   // 4 nt tiles per row block
    if (t == 0) {
        volatile int* w2d = &g_w2done;
        volatile int* c1  = &g_cnt1[row];
        while (*w2d < W2_BLKS) __nanosleep(128);
        while (*c1 < 8)        __nanosleep(128);
        __threadfence();
    }
    __syncthreads();
    gemm_tile_body<H_DIM, false>(tileid, smem, h_in, w2t, b2, out);
}

// ---------------- launch --------------------------------------------------------
extern "C" void kernel_launch(void* const* d_in, const int* in_sizes, int n_in,
                              void* d_out, int out_size) {
    const float* hs = (const float*)d_in[0];
    const float* wg = (const float*)d_in[1];
    const float* w1 = (const float*)d_in[2];   // [E, M, H]
    const float* b1 = (const float*)d_in[3];
    const float* w2 = (const float*)d_in[4];   // [E, H, M]
    const float* b2 = (const float*)d_in[5];
    float* out = (float*)d_out;

    constexpr int SMEM_BYTES = 3 * 32768;
    cudaFuncSetAttribute(moe_ffn_fused,
                         cudaFuncAttributeMaxDynamicSharedMemorySize, SMEM_BYTES);

    __half *a_p, *h_p, *w1t_p, *w2t_p;
    cudaGetSymbolAddress((void**)&a_p,   g_a);
    cudaGetSymbolAddress((void**)&h_p,   g_h);
    cudaGetSymbolAddress((void**)&w1t_p, g_w1t);
    cudaGetSymbolAddress((void**)&w2t_p, g_w2t);

    int write_laux = (out_size > S_TOK * M_DIM) ? 1 : 0;

    // 1) gate + w1 transpose (one launch, block roles)
    prep_kernel<<<S_TOK / 8 + 4096, 256>>>(hs, wg, w1);
    // 2) capacity scan + fused l_aux + dependency-counter reset
    scan_kernel<<<1, 1024>>>(out + (size_t)S_TOK * M_DIM, write_laux);
    // 3) gather + zero-dropped (one launch)
    gather_zero_kernel<<<N_EXP * CAP + S_TOK / 4, 128>>>(hs, out);
    // 4) fused FFN: GEMM1 + w2 transpose + GEMM2 in one grid
    moe_ffn_fused<<<G1_TILES + W2_BLKS + G2_TILES, 128, SMEM_BYTES>>>(
        a_p, w1t_p, b1, h_p, w2t_p, b2, w2, out);
}

// round 16
// speedup vs baseline: 1.1311x; 1.1311x over previous
#include <cuda_runtime.h>
#include <cuda_bf16.h>
#include <cuda_fp16.h>
#include <cstdint>
#include <cstddef>

// Problem constants
#define S_TOK 8192
#define M_DIM 512
#define H_DIM 1024
#define N_EXP 8
#define CAP   1024

// ---------------- portable PTX helpers (sm_103 baseline) ------------------------
__device__ __forceinline__ uint32_t smem_to_u32(const void* p) {
    uint32_t a;
    asm("{ .reg .u64 t; cvta.to.shared.u64 t, %1; cvt.u32.u64 %0, t; }" : "=r"(a) : "l"(p));
    return a;
}
#define CP_ASYNC16(dst, src) \
    asm volatile("cp.async.cg.shared.global [%0], [%1], 16;" :: "r"(dst), "l"(src))
#define CP_COMMIT() asm volatile("cp.async.commit_group;" ::: "memory")
#define CP_WAIT1()  asm volatile("cp.async.wait_group 1;" ::: "memory")
#define CP_WAIT0()  asm volatile("cp.async.wait_group 0;" ::: "memory")
#define LDSM_X4(r, addr) \
    asm volatile("ldmatrix.sync.aligned.m8n8.x4.shared.b16 {%0,%1,%2,%3}, [%4];" \
        : "=r"((r)[0]), "=r"((r)[1]), "=r"((r)[2]), "=r"((r)[3]) : "r"(addr))
#define MMA_F16(c, a, b0, b1) \
    asm volatile("mma.sync.aligned.m16n8k16.row.col.f32.f16.f16.f32 " \
        "{%0,%1,%2,%3}, {%4,%5,%6,%7}, {%8,%9}, {%0,%1,%2,%3};" \
        : "+f"((c)[0]), "+f"((c)[1]), "+f"((c)[2]), "+f"((c)[3]) \
        : "r"((a)[0]), "r"((a)[1]), "r"((a)[2]), "r"((a)[3]), "r"(b0), "r"(b1))

// ---------------- device scratch ------------------------------------------------
__device__ __half g_a[(size_t)N_EXP * CAP * M_DIM];            // gathered tokens fp16
__device__ __half g_h[(size_t)N_EXP * CAP * H_DIM];            // hidden fp16
__device__ __half g_w1t[(size_t)N_EXP * H_DIM * M_DIM];        // w1^T fp16 [E,H,M]
__device__ __half g_w2t[(size_t)N_EXP * M_DIM * H_DIM];        // w2^T fp16 [E,M,H]
__device__ float g_gates[(size_t)S_TOK * N_EXP];
__device__ float g_gate[S_TOK];
__device__ int   g_expert[S_TOK];
__device__ int   g_loc[S_TOK];
__device__ int   g_slot[N_EXP * CAP];

// ---------------- 1) fused prep: gate + w1 transpose ----------------------------
// Block roles: [0,1024) gate (8 tokens each); [1024,5120) w1 [E,M,H]->[E,H,M].
__global__ void prep_kernel(const float* __restrict__ feats, const float* __restrict__ wg,
                            const float* __restrict__ w1) {
    __shared__ float sh[N_EXP * M_DIM];   // 16KB
    int bid = blockIdx.x;
    int tid = threadIdx.x;

    if (bid < S_TOK / 8) {
        // ---- gate role ----
        for (int i = tid; i < N_EXP * M_DIM; i += 256) {
            int m = i & (M_DIM - 1);
            int e = i >> 9;
            sh[e * M_DIM + m] = wg[m * N_EXP + e];
        }
        __syncthreads();
        int warp = tid >> 5, lane = tid & 31;
        int s = bid * 8 + warp;
        const float* frow = feats + (size_t)s * M_DIM;
        float x[16];
#pragma unroll
        for (int j = 0; j < 16; j++) x[j] = frow[lane + 32 * j];
        float logit[N_EXP];
#pragma unroll
        for (int e = 0; e < N_EXP; e++) {
            const float* w = sh + e * M_DIM;
            float acc = 0.f;
#pragma unroll
            for (int j = 0; j < 16; j++) acc += x[j] * w[lane + 32 * j];
#pragma unroll
            for (int off = 16; off > 0; off >>= 1)
                acc += __shfl_down_sync(0xffffffffu, acc, off);
            logit[e] = acc;
        }
        if (lane == 0) {
            float mx = logit[0]; int am = 0;
#pragma unroll
            for (int e = 1; e < N_EXP; e++)
                if (logit[e] > mx) { mx = logit[e]; am = e; }
            float ex[N_EXP]; float se = 0.f;
#pragma unroll
            for (int e = 0; e < N_EXP; e++) { ex[e] = expf(logit[e] - mx); se += ex[e]; }
            float inv = 1.f / se;
#pragma unroll
            for (int e = 0; e < N_EXP; e++) g_gates[(size_t)s * N_EXP + e] = ex[e] * inv;
            g_expert[s] = am;
            g_gate[s]   = ex[am] * inv;
        }
        return;
    }

    // ---- w1 transpose role: [E,M,H] -> [E,H,M], 32x32 tiles --------------------
    int tb = bid - S_TOK / 8;
    const int R = M_DIM, C = H_DIM;
    int cx = tb & 31, cy = (tb >> 5) & 15, e = tb >> 9;
    int r0 = cy * 32, c0 = cx * 32;
    float (*t)[33] = (float(*)[33])sh;
    int tx = tid & 31, ty = tid >> 5;        // 32 x 8
    const float* ine = w1 + (size_t)e * R * C;
#pragma unroll
    for (int i = 0; i < 4; i++)
        t[ty + i * 8][tx] = ine[(size_t)(r0 + ty + i * 8) * C + c0 + tx];
    __syncthreads();
    __half* oe = g_w1t + (size_t)e * R * C;
#pragma unroll
    for (int it = 0; it < 2; it++) {
        int idx = it * 256 + tid;
        int ci  = idx >> 4;
        int rp  = (idx & 15) * 2;
        __half2 v = __floats2half2_rn(t[rp][ci], t[rp + 1][ci]);
        *(__half2*)(oe + (size_t)(c0 + ci) * R + r0 + rp) = v;
    }
}

// ---------------- 2) scan + l_aux + w2 transpose (one launch) -------------------
// bid 0: capacity scan + fused l_aux (1024 threads, 32 warp-blocks of 256 tokens).
// bids [1,513): w2 [E,H,M]->[E,M,H] transpose, 8 32x32 tiles per block
// (8 sub-blocks of 128 threads). The transposes fill the 147 SMs that the
// single-block scan leaves idle.
__global__ void scan_xpose_kernel(const float* __restrict__ w2,
                                  float* __restrict__ laux_out, int write_laux) {
    __shared__ __align__(16) char sbuf[40960];   // union: scan state / 8 transpose tiles
    int bid = blockIdx.x;
    int tid = threadIdx.x;

    if (bid > 0) {
        // ---- w2 transpose role ----
        int sub = tid >> 7, st = tid & 127;
        int tb = (bid - 1) * 8 + sub;            // tile 0..4095
        const int R = H_DIM, C = M_DIM;
        int cx = tb & 15, cy = (tb >> 4) & 31, e = tb >> 9;
        int r0 = cy * 32, c0 = cx * 32;
        float (*tt)[33] = ((float(*)[32][33])sbuf)[sub];
        int tx = st & 31, ty = st >> 5;          // 32 x 4
        const float* ine = w2 + (size_t)e * R * C;
#pragma unroll
        for (int i = 0; i < 8; i++)
            tt[ty + i * 4][tx] = ine[(size_t)(r0 + ty + i * 4) * C + c0 + tx];
        __syncthreads();
        __half* oe = g_w2t + (size_t)e * R * C;
#pragma unroll
        for (int it = 0; it < 4; it++) {
            int idx = it * 128 + st;
            int ci  = idx >> 4;
            int rp  = (idx & 15) * 2;
            __half2 v = __floats2half2_rn(tt[rp][ci], tt[rp + 1][ci]);
            *(__half2*)(oe + (size_t)(c0 + ci) * R + r0 + rp) = v;
        }
        return;
    }

    // ---- scan role (bid 0) ----
    int* sexp = (int*)sbuf;                              // 32KB
    int (*cnt)[N_EXP] = (int(*)[N_EXP])(sbuf + 32768);   // 1KB
    int (*off)[N_EXP] = (int(*)[N_EXP])(sbuf + 33792);   // 1KB
    int* tot = (int*)(sbuf + 34816);                     // 32B
    float* red = (float*)(sbuf + 34848);                 // 4KB (ends 38944 <= 40960)
    int warp = tid >> 5, lane = tid & 31;
    unsigned ltmask = (lane == 0) ? 0u : (0xffffffffu >> (32 - lane));

    for (int i = tid; i < S_TOK; i += 1024) sexp[i] = g_expert[i];
    for (int i = tid; i < N_EXP * CAP; i += 1024) g_slot[i] = -1;
    __syncthreads();

    // Phase 1: counts
    {
        int run[N_EXP];
#pragma unroll
        for (int e = 0; e < N_EXP; e++) run[e] = 0;
#pragma unroll
        for (int it = 0; it < 8; it++) {
            int s = warp * 256 + it * 32 + lane;
            int e = sexp[s];
#pragma unroll
            for (int eq = 0; eq < N_EXP; eq++) {
                unsigned bal = __ballot_sync(0xffffffffu, e == eq);
                run[eq] += __popc(bal);
            }
        }
        if (lane < N_EXP) cnt[warp][lane] = run[lane];
    }
    __syncthreads();

    // Phase 2: exclusive prefix + totals
    if (tid < 256) {
        int w = tid >> 3, e = tid & 7;
        int acc = 0;
        for (int wp = 0; wp < w; wp++) acc += cnt[wp][e];
        off[w][e] = acc;
        if (w == 31) tot[e] = acc + cnt[31][e];
    }
    __syncthreads();

    // Phase 3: assignment
    {
        int run[N_EXP];
#pragma unroll
        for (int e = 0; e < N_EXP; e++) run[e] = off[warp][e];
#pragma unroll
        for (int it = 0; it < 8; it++) {
            int s = warp * 256 + it * 32 + lane;
            int e = sexp[s];
            int myrank = 0;
            unsigned bals[N_EXP];
#pragma unroll
            for (int eq = 0; eq < N_EXP; eq++) {
                bals[eq] = __ballot_sync(0xffffffffu, e == eq);
                if (e == eq) myrank = __popc(bals[eq] & ltmask);
            }
            int loc = run[e] + myrank;
            g_loc[s] = loc;
            if (loc < CAP) g_slot[e * CAP + loc] = s;
#pragma unroll
            for (int eq = 0; eq < N_EXP; eq++) run[eq] += __popc(bals[eq]);
        }
    }

    // Fused l_aux
    if (!write_laux) return;
    float w[N_EXP];
#pragma unroll
    for (int e = 0; e < N_EXP; e++) w[e] = (float)min(tot[e], CAP);
    float acc = 0.f;
    for (int s = tid; s < S_TOK; s += 1024) {
        const float4* gp = (const float4*)(g_gates + (size_t)s * N_EXP);
        float4 a = gp[0], b = gp[1];
        acc += a.x * w[0] + a.y * w[1] + a.z * w[2] + a.w * w[3]
             + b.x * w[4] + b.y * w[5] + b.z * w[6] + b.w * w[7];
    }
    red[tid] = acc;
    __syncthreads();
    for (int st = 512; st > 0; st >>= 1) {
        if (tid < st) red[tid] += red[tid + st];
        __syncthreads();
    }
    if (tid == 0)
        *laux_out = red[0] * (float)N_EXP / ((float)S_TOK * (float)S_TOK);
}

// ---------------- 3) fused gather + zero-dropped --------------------------------
__global__ void gather_zero_kernel(const float* __restrict__ feats, float* __restrict__ out) {
    int bid = blockIdx.x;
    int tid = threadIdx.x;   // 128
    if (bid < N_EXP * CAP) {
        int token = g_slot[bid];
        float4 v = make_float4(0.f, 0.f, 0.f, 0.f);
        if (token >= 0) v = ((const float4*)(feats + (size_t)token * M_DIM))[tid];
        __half2 h01 = __floats2half2_rn(v.x, v.y);
        __half2 h23 = __floats2half2_rn(v.z, v.w);
        uint2 hv;
        hv.x = *reinterpret_cast<uint32_t*>(&h01);
        hv.y = *reinterpret_cast<uint32_t*>(&h23);
        ((uint2*)(g_a + (size_t)bid * M_DIM))[tid] = hv;
    } else {
        int s = (bid - N_EXP * CAP) * 4 + (tid >> 5);
        if (g_loc[s] < CAP) return;
        int lane = tid & 31;
        float4* row = (float4*)(out + (size_t)s * M_DIM);
#pragma unroll
        for (int i = 0; i < 4; i++)
            row[lane + 32 * i] = make_float4(0.f, 0.f, 0.f, 0.f);
    }
}

// ---------------- GEMM tile body (shared by both GEMMs) -------------------------
template <int KTOT, bool IS_G1>
__device__ __forceinline__ void gemm_tile_body(
    int tileid, char* smem,
    const __half* __restrict__ a_in, const __half* __restrict__ b_in,
    const float* __restrict__ bias, float* __restrict__ out) {
    constexpr int NTOT = IS_G1 ? H_DIM : M_DIM;
    constexpr int BK = 64;
    constexpr int NC = KTOT / BK;
    constexpr int STG = 32768;
    const uint32_t sbu = smem_to_u32(smem);
    const int t = threadIdx.x;
    const int lane = t & 31, wid = t >> 5;
    const int wm = wid >> 1, wn = wid & 1;
    const int nt = tileid % (NTOT / 128);
    const int mt = (tileid / (NTOT / 128)) % (CAP / 128);
    const int e  = tileid / ((NTOT / 128) * (CAP / 128));

    const __half* srcs[2] = {
        a_in + ((size_t)e * CAP  + mt * 128) * KTOT,
        b_in + ((size_t)e * NTOT + nt * 128) * KTOT};

    auto load_stage = [&](int c, int stg) {
        int k0 = c * BK;
        uint32_t sb = sbu + stg * STG;
#pragma unroll
        for (int i = 0; i < 16; i++) {
            int idx  = i * 128 + t;
            int tile = idx >> 10;
            int rem  = idx & 1023;
            int row  = rem >> 3;
            int seg  = rem & 7;
            const __half* src = srcs[tile] + (size_t)row * KTOT + k0 + seg * 8;
            uint32_t dst = sb + tile * 16384 + row * 128 + (((seg ^ (row & 7))) << 4);
            CP_ASYNC16(dst, src);
        }
        CP_COMMIT();
    };

    float acc[4][8][4];
#pragma unroll
    for (int i = 0; i < 4; i++)
#pragma unroll
        for (int j = 0; j < 8; j++)
#pragma unroll
            for (int k = 0; k < 4; k++) acc[i][j][k] = 0.f;

    load_stage(0, 0);
    load_stage(1, 1);

    const int a_m = wm * 64 + (lane & 15);
    const int b_n = wn * 64 + ((lane >> 3) & 1) * 8 + (lane & 7);
    const int k8l = lane >> 4;

    for (int c = 0; c < NC; c++) {
        if (c >= NC - 1) { CP_WAIT0(); } else { CP_WAIT1(); }
        __syncthreads();
        if (c + 2 < NC) load_stage(c + 2, (c + 2) % 3);

        uint32_t sb = sbu + (c % 3) * STG;
#pragma unroll
        for (int ks = 0; ks < 4; ks++) {
            int seg = ks * 2 + k8l;
            uint32_t A[4][4], B[4][4];
#pragma unroll
            for (int mf = 0; mf < 4; mf++) {
                int m = a_m + mf * 16;
                LDSM_X4(A[mf], sb + m * 128 + ((seg ^ (m & 7)) << 4));
            }
#pragma unroll
            for (int p = 0; p < 4; p++) {
                int n = b_n + p * 16;
                LDSM_X4(B[p], sb + 16384 + n * 128 + ((seg ^ (n & 7)) << 4));
            }
#pragma unroll
            for (int mf = 0; mf < 4; mf++) {
#pragma unroll
                for (int p = 0; p < 4; p++) {
                    MMA_F16(acc[mf][2 * p + 0], A[mf], B[p][0], B[p][2]);
                    MMA_F16(acc[mf][2 * p + 1], A[mf], B[p][1], B[p][3]);
                }
            }
        }
    }

    const int g = lane >> 2, q = lane & 3;
    if (IS_G1) {
#pragma unroll
        for (int mf = 0; mf < 4; mf++) {
#pragma unroll
            for (int h = 0; h < 2; h++) {
                int slotrow = mt * 128 + wm * 64 + mf * 16 + g + h * 8;
                size_t rowbase = ((size_t)e * CAP + slotrow) * H_DIM;
#pragma unroll
                for (int nf = 0; nf < 8; nf++) {
                    int col = nt * 128 + wn * 64 + nf * 8 + q * 2;
                    float v0 = fmaxf(acc[mf][nf][2 * h + 0] + __ldg(&bias[e * NTOT + col]),     0.f);
                    float v1 = fmaxf(acc[mf][nf][2 * h + 1] + __ldg(&bias[e * NTOT + col + 1]), 0.f);
                    __half2 hh = __floats2half2_rn(v0, v1);
                    *reinterpret_cast<uint32_t*>(&g_h[rowbase + col]) =
                        *reinterpret_cast<uint32_t*>(&hh);
                }
            }
        }
    } else {
#pragma unroll
        for (int mf = 0; mf < 4; mf++) {
#pragma unroll
            for (int h = 0; h < 2; h++) {
                int slotrow = mt * 128 + wm * 64 + mf * 16 + g + h * 8;
                int token = g_slot[e * CAP + slotrow];
                if (token < 0) continue;
                float gt = g_gate[token];
                float* orow = out + (size_t)token * M_DIM;
#pragma unroll
                for (int nf = 0; nf < 8; nf++) {
                    int col = nt * 128 + wn * 64 + nf * 8 + q * 2;
                    float2 v;
                    v.x = (acc[mf][nf][2 * h + 0] + __ldg(&bias[e * NTOT + col]))     * gt;
                    v.y = (acc[mf][nf][2 * h + 1] + __ldg(&bias[e * NTOT + col + 1])) * gt;
                    *(float2*)(orow + col) = v;
                }
            }
        }
    }
}

// ---------------- 4) GEMM wrappers ----------------------------------------------
__global__ void __launch_bounds__(128, 2)
moe_gemm1(const __half* __restrict__ a_in, const __half* __restrict__ w1t,
          const float* __restrict__ b1) {
    extern __shared__ __align__(1024) char smem[];
    gemm_tile_body<M_DIM, true>(blockIdx.x, smem, a_in, w1t, b1, nullptr);
}

__global__ void __launch_bounds__(128, 2)
moe_gemm2(const __half* __restrict__ h_in, const __half* __restrict__ w2t,
          const float* __restrict__ b2, float* __restrict__ out) {
    extern __shared__ __align__(1024) char smem[];
    gemm_tile_body<H_DIM, false>(blockIdx.x, smem, h_in, w2t, b2, out);
}

// ---------------- launch --------------------------------------------------------
extern "C" void kernel_launch(void* const* d_in, const int* in_sizes, int n_in,
                              void* d_out, int out_size) {
    const float* hs = (const float*)d_in[0];
    const float* wg = (const float*)d_in[1];
    const float* w1 = (const float*)d_in[2];   // [E, M, H]
    const float* b1 = (const float*)d_in[3];
    const float* w2 = (const float*)d_in[4];   // [E, H, M]
    const float* b2 = (const float*)d_in[5];
    float* out = (float*)d_out;

    constexpr int SMEM_BYTES = 3 * 32768;
    cudaFuncSetAttribute(moe_gemm1, cudaFuncAttributeMaxDynamicSharedMemorySize, SMEM_BYTES);
    cudaFuncSetAttribute(moe_gemm2, cudaFuncAttributeMaxDynamicSharedMemorySize, SMEM_BYTES);

    __half *a_p, *h_p, *w1t_p, *w2t_p;
    cudaGetSymbolAddress((void**)&a_p,   g_a);
    cudaGetSymbolAddress((void**)&h_p,   g_h);
    cudaGetSymbolAddress((void**)&w1t_p, g_w1t);
    cudaGetSymbolAddress((void**)&w2t_p, g_w2t);

    int write_laux = (out_size > S_TOK * M_DIM) ? 1 : 0;

    // 1) gate + w1 transpose (block roles)
    prep_kernel<<<S_TOK / 8 + 4096, 256>>>(hs, wg, w1);
    // 2) scan + l_aux (bid 0) overlapped with w2 transpose (bids 1..512)
    scan_xpose_kernel<<<1 + 512, 1024>>>(w2, out + (size_t)S_TOK * M_DIM, write_laux);
    // 3) gather + zero-dropped
    gather_zero_kernel<<<N_EXP * CAP + S_TOK / 4, 128>>>(hs, out);
    // 4) expert FFN
    moe_gemm1<<<512, 128, SMEM_BYTES>>>(a_p, w1t_p, b1);
    moe_gemm2<<<256, 128, SMEM_BYTES>>>(h_p, w2t_p, b2, out);
}

// round 17
// speedup vs baseline: 1.1527x; 1.0191x over previous
#include <cuda_runtime.h>
#include <cuda_bf16.h>
#include <cuda_fp16.h>
#include <cstdint>
#include <cstddef>

// Problem constants
#define S_TOK 8192
#define M_DIM 512
#define H_DIM 1024
#define N_EXP 8
#define CAP   1024

// ---------------- portable PTX helpers (sm_103 baseline) ------------------------
__device__ __forceinline__ uint32_t smem_to_u32(const void* p) {
    uint32_t a;
    asm("{ .reg .u64 t; cvta.to.shared.u64 t, %1; cvt.u32.u64 %0, t; }" : "=r"(a) : "l"(p));
    return a;
}
#define CP_ASYNC16(dst, src) \
    asm volatile("cp.async.cg.shared.global [%0], [%1], 16;" :: "r"(dst), "l"(src))
#define CP_COMMIT() asm volatile("cp.async.commit_group;" ::: "memory")
#define CP_WAIT1()  asm volatile("cp.async.wait_group 1;" ::: "memory")
#define CP_WAIT0()  asm volatile("cp.async.wait_group 0;" ::: "memory")
#define LDSM_X4(r, addr) \
    asm volatile("ldmatrix.sync.aligned.m8n8.x4.shared.b16 {%0,%1,%2,%3}, [%4];" \
        : "=r"((r)[0]), "=r"((r)[1]), "=r"((r)[2]), "=r"((r)[3]) : "r"(addr))
#define MMA_F16(c, a, b0, b1) \
    asm volatile("mma.sync.aligned.m16n8k16.row.col.f32.f16.f16.f32 " \
        "{%0,%1,%2,%3}, {%4,%5,%6,%7}, {%8,%9}, {%0,%1,%2,%3};" \
        : "+f"((c)[0]), "+f"((c)[1]), "+f"((c)[2]), "+f"((c)[3]) \
        : "r"((a)[0]), "r"((a)[1]), "r"((a)[2]), "r"((a)[3]), "r"(b0), "r"(b1))

// ---------------- device scratch ------------------------------------------------
__device__ __half g_a[(size_t)N_EXP * CAP * M_DIM];            // gathered tokens fp16
__device__ __half g_h[(size_t)N_EXP * CAP * H_DIM];            // hidden fp16
__device__ __half g_w1t[(size_t)N_EXP * H_DIM * M_DIM];        // w1^T fp16 [E,H,M]
__device__ __half g_w2t[(size_t)N_EXP * M_DIM * H_DIM];        // w2^T fp16 [E,M,H]
__device__ float g_gates[(size_t)S_TOK * N_EXP];
__device__ float g_gate[S_TOK];
__device__ int   g_expert[S_TOK];
__device__ int   g_loc[S_TOK];
__device__ int   g_slot[N_EXP * CAP];

// ---------------- 1) fused prep: gate + w1 transpose ----------------------------
// Block roles: [0,1024) gate (8 tokens each); [1024,5120) w1 [E,M,H]->[E,H,M].
__global__ void prep_kernel(const float* __restrict__ feats, const float* __restrict__ wg,
                            const float* __restrict__ w1) {
    __shared__ float sh[N_EXP * M_DIM];   // 16KB
    int bid = blockIdx.x;
    int tid = threadIdx.x;

    if (bid < S_TOK / 8) {
        // ---- gate role (numerics deliberately identical to prior rounds) ------
        for (int i = tid; i < N_EXP * M_DIM; i += 256) {
            int m = i & (M_DIM - 1);
            int e = i >> 9;
            sh[e * M_DIM + m] = wg[m * N_EXP + e];
        }
        __syncthreads();
        int warp = tid >> 5, lane = tid & 31;
        int s = bid * 8 + warp;
        const float* frow = feats + (size_t)s * M_DIM;
        float x[16];
#pragma unroll
        for (int j = 0; j < 16; j++) x[j] = frow[lane + 32 * j];
        float logit[N_EXP];
#pragma unroll
        for (int e = 0; e < N_EXP; e++) {
            const float* w = sh + e * M_DIM;
            float acc = 0.f;
#pragma unroll
            for (int j = 0; j < 16; j++) acc += x[j] * w[lane + 32 * j];
#pragma unroll
            for (int off = 16; off > 0; off >>= 1)
                acc += __shfl_down_sync(0xffffffffu, acc, off);
            logit[e] = acc;
        }
        if (lane == 0) {
            float mx = logit[0]; int am = 0;
#pragma unroll
            for (int e = 1; e < N_EXP; e++)
                if (logit[e] > mx) { mx = logit[e]; am = e; }
            float ex[N_EXP]; float se = 0.f;
#pragma unroll
            for (int e = 0; e < N_EXP; e++) { ex[e] = expf(logit[e] - mx); se += ex[e]; }
            float inv = 1.f / se;
#pragma unroll
            for (int e = 0; e < N_EXP; e++) g_gates[(size_t)s * N_EXP + e] = ex[e] * inv;
            g_expert[s] = am;
            g_gate[s]   = ex[am] * inv;
        }
        return;
    }

    // ---- w1 transpose role: [E,M,H] -> [E,H,M], 32x32 tiles, float4 loads ------
    int tb = bid - S_TOK / 8;
    const int R = M_DIM, C = H_DIM;
    int cx = tb & 31, cy = (tb >> 5) & 15, e = tb >> 9;
    int r0 = cy * 32, c0 = cx * 32;
    float (*t)[33] = (float(*)[33])sh;
    const float* ine = w1 + (size_t)e * R * C;
    {
        // 256 threads x 1 float4 = 1024 floats = full 32x32 tile
        int r  = tid >> 3;             // 0..31
        int c4 = (tid & 7) * 4;        // 0,4,...,28
        float4 v = *(const float4*)(ine + (size_t)(r0 + r) * C + c0 + c4);
        t[r][c4 + 0] = v.x; t[r][c4 + 1] = v.y;
        t[r][c4 + 2] = v.z; t[r][c4 + 3] = v.w;
    }
    __syncthreads();
    __half* oe = g_w1t + (size_t)e * R * C;
#pragma unroll
    for (int it = 0; it < 2; it++) {
        int idx = it * 256 + tid;
        int ci  = idx >> 4;
        int rp  = (idx & 15) * 2;
        __half2 v = __floats2half2_rn(t[rp][ci], t[rp + 1][ci]);
        *(__half2*)(oe + (size_t)(c0 + ci) * R + r0 + rp) = v;
    }
}

// ---------------- 2) scan + l_aux + w2 transpose (one launch) -------------------
// bid 0: capacity scan + fused l_aux. bids [1,513): w2 transpose, 8 tiles/block,
// float4 loads. Transposes fill the 147 SMs the single-block scan leaves idle.
__global__ void scan_xpose_kernel(const float* __restrict__ w2,
                                  float* __restrict__ laux_out, int write_laux) {
    __shared__ __align__(16) char sbuf[40960];   // union: scan state / 8 transpose tiles
    int bid = blockIdx.x;
    int tid = threadIdx.x;

    if (bid > 0) {
        // ---- w2 transpose role (float4 loads) ----
        int sub = tid >> 7, st = tid & 127;
        int tb = (bid - 1) * 8 + sub;            // tile 0..4095
        const int R = H_DIM, C = M_DIM;
        int cx = tb & 15, cy = (tb >> 4) & 31, e = tb >> 9;
        int r0 = cy * 32, c0 = cx * 32;
        float (*tt)[33] = ((float(*)[32][33])sbuf)[sub];
        const float* ine = w2 + (size_t)e * R * C;
#pragma unroll
        for (int k = 0; k < 2; k++) {
            int idx = k * 128 + st;              // 0..255
            int r   = idx >> 3;                  // 0..31
            int c4  = (idx & 7) * 4;
            float4 v = *(const float4*)(ine + (size_t)(r0 + r) * C + c0 + c4);
            tt[r][c4 + 0] = v.x; tt[r][c4 + 1] = v.y;
            tt[r][c4 + 2] = v.z; tt[r][c4 + 3] = v.w;
        }
        __syncthreads();
        __half* oe = g_w2t + (size_t)e * R * C;
#pragma unroll
        for (int it = 0; it < 4; it++) {
            int idx = it * 128 + st;
            int ci  = idx >> 4;
            int rp  = (idx & 15) * 2;
            __half2 v = __floats2half2_rn(tt[rp][ci], tt[rp + 1][ci]);
            *(__half2*)(oe + (size_t)(c0 + ci) * R + r0 + rp) = v;
        }
        return;
    }

    // ---- scan role (bid 0) ----
    int* sexp = (int*)sbuf;                              // 32KB
    int (*cnt)[N_EXP] = (int(*)[N_EXP])(sbuf + 32768);   // 1KB
    int (*off)[N_EXP] = (int(*)[N_EXP])(sbuf + 33792);   // 1KB
    int* tot = (int*)(sbuf + 34816);                     // 32B
    float* red = (float*)(sbuf + 34848);                 // 4KB
    int warp = tid >> 5, lane = tid & 31;
    unsigned ltmask = (lane == 0) ? 0u : (0xffffffffu >> (32 - lane));

    for (int i = tid; i < S_TOK; i += 1024) sexp[i] = g_expert[i];
    for (int i = tid; i < N_EXP * CAP; i += 1024) g_slot[i] = -1;
    __syncthreads();

    // Phase 1: counts
    {
        int run[N_EXP];
#pragma unroll
        for (int e = 0; e < N_EXP; e++) run[e] = 0;
#pragma unroll
        for (int it = 0; it < 8; it++) {
            int s = warp * 256 + it * 32 + lane;
            int e = sexp[s];
#pragma unroll
            for (int eq = 0; eq < N_EXP; eq++) {
                unsigned bal = __ballot_sync(0xffffffffu, e == eq);
                run[eq] += __popc(bal);
            }
        }
        if (lane < N_EXP) cnt[warp][lane] = run[lane];
    }
    __syncthreads();

    // Phase 2: exclusive prefix + totals
    if (tid < 256) {
        int w = tid >> 3, e = tid & 7;
        int acc = 0;
        for (int wp = 0; wp < w; wp++) acc += cnt[wp][e];
        off[w][e] = acc;
        if (w == 31) tot[e] = acc + cnt[31][e];
    }
    __syncthreads();

    // Phase 3: assignment
    {
        int run[N_EXP];
#pragma unroll
        for (int e = 0; e < N_EXP; e++) run[e] = off[warp][e];
#pragma unroll
        for (int it = 0; it < 8; it++) {
            int s = warp * 256 + it * 32 + lane;
            int e = sexp[s];
            int myrank = 0;
            unsigned bals[N_EXP];
#pragma unroll
            for (int eq = 0; eq < N_EXP; eq++) {
                bals[eq] = __ballot_sync(0xffffffffu, e == eq);
                if (e == eq) myrank = __popc(bals[eq] & ltmask);
            }
            int loc = run[e] + myrank;
            g_loc[s] = loc;
            if (loc < CAP) g_slot[e * CAP + loc] = s;
#pragma unroll
            for (int eq = 0; eq < N_EXP; eq++) run[eq] += __popc(bals[eq]);
        }
    }

    // Fused l_aux
    if (!write_laux) return;
    float w[N_EXP];
#pragma unroll
    for (int e = 0; e < N_EXP; e++) w[e] = (float)min(tot[e], CAP);
    float acc = 0.f;
    for (int s = tid; s < S_TOK; s += 1024) {
        const float4* gp = (const float4*)(g_gates + (size_t)s * N_EXP);
        float4 a = gp[0], b = gp[1];
        acc += a.x * w[0] + a.y * w[1] + a.z * w[2] + a.w * w[3]
             + b.x * w[4] + b.y * w[5] + b.z * w[6] + b.w * w[7];
    }
    red[tid] = acc;
    __syncthreads();
    for (int st = 512; st > 0; st >>= 1) {
        if (tid < st) red[tid] += red[tid + st];
        __syncthreads();
    }
    if (tid == 0)
        *laux_out = red[0] * (float)N_EXP / ((float)S_TOK * (float)S_TOK);
}

// ---------------- 3) fused gather + zero-dropped --------------------------------
__global__ void gather_zero_kernel(const float* __restrict__ feats, float* __restrict__ out) {
    int bid = blockIdx.x;
    int tid = threadIdx.x;   // 128
    if (bid < N_EXP * CAP) {
        int token = g_slot[bid];
        float4 v = make_float4(0.f, 0.f, 0.f, 0.f);
        if (token >= 0) v = ((const float4*)(feats + (size_t)token * M_DIM))[tid];
        __half2 h01 = __floats2half2_rn(v.x, v.y);
        __half2 h23 = __floats2half2_rn(v.z, v.w);
        uint2 hv;
        hv.x = *reinterpret_cast<uint32_t*>(&h01);
        hv.y = *reinterpret_cast<uint32_t*>(&h23);
        ((uint2*)(g_a + (size_t)bid * M_DIM))[tid] = hv;
    } else {
        int s = (bid - N_EXP * CAP) * 4 + (tid >> 5);
        if (g_loc[s] < CAP) return;
        int lane = tid & 31;
        float4* row = (float4*)(out + (size_t)s * M_DIM);
#pragma unroll
        for (int i = 0; i < 4; i++)
            row[lane + 32 * i] = make_float4(0.f, 0.f, 0.f, 0.f);
    }
}

// ---------------- GEMM tile body (shared by both GEMMs) -------------------------
template <int KTOT, bool IS_G1>
__device__ __forceinline__ void gemm_tile_body(
    int tileid, char* smem,
    const __half* __restrict__ a_in, const __half* __restrict__ b_in,
    const float* __restrict__ bias, float* __restrict__ out) {
    constexpr int NTOT = IS_G1 ? H_DIM : M_DIM;
    constexpr int BK = 64;
    constexpr int NC = KTOT / BK;
    constexpr int STG = 32768;
    const uint32_t sbu = smem_to_u32(smem);
    const int t = threadIdx.x;
    const int lane = t & 31, wid = t >> 5;
    const int wm = wid >> 1, wn = wid & 1;
    const int nt = tileid % (NTOT / 128);
    const int mt = (tileid / (NTOT / 128)) % (CAP / 128);
    const int e  = tileid / ((NTOT / 128) * (CAP / 128));

    const __half* srcs[2] = {
        a_in + ((size_t)e * CAP  + mt * 128) * KTOT,
        b_in + ((size_t)e * NTOT + nt * 128) * KTOT};

    auto load_stage = [&](int c, int stg) {
        int k0 = c * BK;
        uint32_t sb = sbu + stg * STG;
#pragma unroll
        for (int i = 0; i < 16; i++) {
            int idx  = i * 128 + t;
            int tile = idx >> 10;
            int rem  = idx & 1023;
            int row  = rem >> 3;
            int seg  = rem & 7;
            const __half* src = srcs[tile] + (size_t)row * KTOT + k0 + seg * 8;
            uint32_t dst = sb + tile * 16384 + row * 128 + (((seg ^ (row & 7))) << 4);
            CP_ASYNC16(dst, src);
        }
        CP_COMMIT();
    };

    float acc[4][8][4];
#pragma unroll
    for (int i = 0; i < 4; i++)
#pragma unroll
        for (int j = 0; j < 8; j++)
#pragma unroll
            for (int k = 0; k < 4; k++) acc[i][j][k] = 0.f;

    load_stage(0, 0);
    load_stage(1, 1);

    const int a_m = wm * 64 + (lane & 15);
    const int b_n = wn * 64 + ((lane >> 3) & 1) * 8 + (lane & 7);
    const int k8l = lane >> 4;

    for (int c = 0; c < NC; c++) {
        if (c >= NC - 1) { CP_WAIT0(); } else { CP_WAIT1(); }
        __syncthreads();
        if (c + 2 < NC) load_stage(c + 2, (c + 2) % 3);

        uint32_t sb = sbu + (c % 3) * STG;
#pragma unroll
        for (int ks = 0; ks < 4; ks++) {
            int seg = ks * 2 + k8l;
            uint32_t A[4][4], B[4][4];
#pragma unroll
            for (int mf = 0; mf < 4; mf++) {
                int m = a_m + mf * 16;
                LDSM_X4(A[mf], sb + m * 128 + ((seg ^ (m & 7)) << 4));
            }
#pragma unroll
            for (int p = 0; p < 4; p++) {
                int n = b_n + p * 16;
                LDSM_X4(B[p], sb + 16384 + n * 128 + ((seg ^ (n & 7)) << 4));
            }
#pragma unroll
            for (int mf = 0; mf < 4; mf++) {
#pragma unroll
                for (int p = 0; p < 4; p++) {
                    MMA_F16(acc[mf][2 * p + 0], A[mf], B[p][0], B[p][2]);
                    MMA_F16(acc[mf][2 * p + 1], A[mf], B[p][1], B[p][3]);
                }
            }
        }
    }

    // ---- epilogue: preload this thread's 16 bias values, then write ------------
    const int g = lane >> 2, q = lane & 3;
    float bv[16];
#pragma unroll
    for (int nf = 0; nf < 8; nf++) {
        int col = nt * 128 + wn * 64 + nf * 8 + q * 2;
        bv[2 * nf + 0] = __ldg(&bias[e * NTOT + col]);
        bv[2 * nf + 1] = __ldg(&bias[e * NTOT + col + 1]);
    }
    if (IS_G1) {
#pragma unroll
        for (int mf = 0; mf < 4; mf++) {
#pragma unroll
            for (int h = 0; h < 2; h++) {
                int slotrow = mt * 128 + wm * 64 + mf * 16 + g + h * 8;
                size_t rowbase = ((size_t)e * CAP + slotrow) * H_DIM;
#pragma unroll
                for (int nf = 0; nf < 8; nf++) {
                    int col = nt * 128 + wn * 64 + nf * 8 + q * 2;
                    float v0 = fmaxf(acc[mf][nf][2 * h + 0] + bv[2 * nf + 0], 0.f);
                    float v1 = fmaxf(acc[mf][nf][2 * h + 1] + bv[2 * nf + 1], 0.f);
                    __half2 hh = __floats2half2_rn(v0, v1);
                    *reinterpret_cast<uint32_t*>(&g_h[rowbase + col]) =
                        *reinterpret_cast<uint32_t*>(&hh);
                }
            }
        }
    } else {
#pragma unroll
        for (int mf = 0; mf < 4; mf++) {
#pragma unroll
            for (int h = 0; h < 2; h++) {
                int slotrow = mt * 128 + wm * 64 + mf * 16 + g + h * 8;
                int token = g_slot[e * CAP + slotrow];
                if (token < 0) continue;
                float gt = g_gate[token];
                float* orow = out + (size_t)token * M_DIM;
#pragma unroll
                for (int nf = 0; nf < 8; nf++) {
                    int col = nt * 128 + wn * 64 + nf * 8 + q * 2;
                    float2 v;
                    v.x = (acc[mf][nf][2 * h + 0] + bv[2 * nf + 0]) * gt;
                    v.y = (acc[mf][nf][2 * h + 1] + bv[2 * nf + 1]) * gt;
                    *(float2*)(orow + col) = v;
                }
            }
        }
    }
}

// ---------------- 4) GEMM wrappers ----------------------------------------------
__global__ void __launch_bounds__(128, 2)
moe_gemm1(const __half* __restrict__ a_in, const __half* __restrict__ w1t,
          const float* __restrict__ b1) {
    extern __shared__ __align__(1024) char smem[];
    gemm_tile_body<M_DIM, true>(blockIdx.x, smem, a_in, w1t, b1, nullptr);
}

__global__ void __launch_bounds__(128, 2)
moe_gemm2(const __half* __restrict__ h_in, const __half* __restrict__ w2t,
          const float* __restrict__ b2, float* __restrict__ out) {
    extern __shared__ __align__(1024) char smem[];
    gemm_tile_body<H_DIM, false>(blockIdx.x, smem, h_in, w2t, b2, out);
}

// ---------------- launch --------------------------------------------------------
extern "C" void kernel_launch(void* const* d_in, const int* in_sizes, int n_in,
                              void* d_out, int out_size) {
    const float* hs = (const float*)d_in[0];
    const float* wg = (const float*)d_in[1];
    const float* w1 = (const float*)d_in[2];   // [E, M, H]
    const float* b1 = (const float*)d_in[3];
    const float* w2 = (const float*)d_in[4];   // [E, H, M]
    const float* b2 = (const float*)d_in[5];
    float* out = (float*)d_out;

    constexpr int SMEM_BYTES = 3 * 32768;
    cudaFuncSetAttribute(moe_gemm1, cudaFuncAttributeMaxDynamicSharedMemorySize, SMEM_BYTES);
    cudaFuncSetAttribute(moe_gemm2, cudaFuncAttributeMaxDynamicSharedMemorySize, SMEM_BYTES);

    __half *a_p, *h_p, *w1t_p, *w2t_p;
    cudaGetSymbolAddress((void**)&a_p,   g_a);
    cudaGetSymbolAddress((void**)&h_p,   g_h);
    cudaGetSymbolAddress((void**)&w1t_p, g_w1t);
    cudaGetSymbolAddress((void**)&w2t_p, g_w2t);

    int write_laux = (out_size > S_TOK * M_DIM) ? 1 : 0;

    // 1) gate + w1 transpose (block roles, float4 loads)
    prep_kernel<<<S_TOK / 8 + 4096, 256>>>(hs, wg, w1);
    // 2) scan + l_aux (bid 0) overlapped with w2 transpose (bids 1..512)
    scan_xpose_kernel<<<1 + 512, 1024>>>(w2, out + (size_t)S_TOK * M_DIM, write_laux);
    // 3) gather + zero-dropped
    gather_zero_kernel<<<N_EXP * CAP + S_TOK / 4, 128>>>(hs, out);
    // 4) expert FFN
    moe_gemm1<<<512, 128, SMEM_BYTES>>>(a_p, w1t_p, b1);
    moe_gemm2<<<256, 128, SMEM_BYTES>>>(h_p, w2t_p, b2, out);
}